// round 1
// baseline (speedup 1.0000x reference)
#include <cuda_runtime.h>
#include <cuda_bf16.h>

// RWKV WKV scan: one thread per (b, d) channel, sequential over T.
//   a_t = exp(w_t)*a_{t-1} + exp(k_t)
//   b_t = exp(w_t)*b_{t-1} + exp(k_t)*v_t
//   out_t = b_t / a_t
// B*D = 16384 channels -> 128 blocks x 128 threads. Coalesced: warp spans 32
// consecutive d at fixed (b, t) -> one 128B line per tensor per step.
// Software-pipelined prefetch of U timesteps to build MLP (only ~3.5 warps/SM).

#define BATCH 16
#define TLEN  2048
#define DIM   1024
#define UNR   8

__global__ __launch_bounds__(128, 1)
void wkv_scan_kernel(const float* __restrict__ K,
                     const float* __restrict__ V,
                     const float* __restrict__ W,
                     float* __restrict__ O) {
    const int c = blockIdx.x * blockDim.x + threadIdx.x;   // channel 0..16383
    const int b = c >> 10;            // / DIM
    const int d = c & (DIM - 1);      // % DIM

    const size_t base = (size_t)b * (size_t)TLEN * (size_t)DIM + (size_t)d;
    const float* kp = K + base;
    const float* vp = V + base;
    const float* wp = W + base;
    float*       op = O + base;

    float a = 0.0f;
    float s = 0.0f;

    float kb[UNR], vb[UNR], wb[UNR];

    // Prologue: prefetch chunk 0
#pragma unroll
    for (int i = 0; i < UNR; ++i) {
        kb[i] = kp[i * DIM];
        vb[i] = vp[i * DIM];
        wb[i] = wp[i * DIM];
    }

    const int NCHUNK = TLEN / UNR;
    for (int ch = 0; ch < NCHUNK; ++ch) {
        float kn[UNR], vn[UNR], wn[UNR];
        if (ch + 1 < NCHUNK) {
            // Prefetch next chunk: 3*UNR independent LDGs issued before compute.
#pragma unroll
            for (int i = 0; i < UNR; ++i) {
                kn[i] = kp[(UNR + i) * DIM];
                vn[i] = vp[(UNR + i) * DIM];
                wn[i] = wp[(UNR + i) * DIM];
            }
        } else {
#pragma unroll
            for (int i = 0; i < UNR; ++i) { kn[i] = 0.0f; vn[i] = 0.0f; wn[i] = 0.0f; }
        }

        // Compute current chunk (loads already resident in registers).
#pragma unroll
        for (int i = 0; i < UNR; ++i) {
            const float ew = __expf(wb[i]);
            const float ek = __expf(kb[i]);
            a = fmaf(ew, a, ek);
            s = fmaf(ew, s, ek * vb[i]);
            op[i * DIM] = __fdividef(s, a);
        }

        kp += UNR * DIM;
        vp += UNR * DIM;
        wp += UNR * DIM;
        op += UNR * DIM;

#pragma unroll
        for (int i = 0; i < UNR; ++i) {
            kb[i] = kn[i];
            vb[i] = vn[i];
            wb[i] = wn[i];
        }
    }
}

extern "C" void kernel_launch(void* const* d_in, const int* in_sizes, int n_in,
                              void* d_out, int out_size) {
    const float* K = (const float*)d_in[0];
    const float* V = (const float*)d_in[1];
    const float* W = (const float*)d_in[2];
    float*       O = (float*)d_out;

    const int threads = 128;
    const int blocks  = (BATCH * DIM) / threads;  // 128
    wkv_scan_kernel<<<blocks, threads>>>(K, V, W, O);
}

// round 3
// speedup vs baseline: 1.6096x; 1.6096x over previous
#include <cuda_runtime.h>
#include <cuda_bf16.h>

// RWKV WKV scan via 3-phase segmented scan over T.
// Step op: (p, qa, qb) = (exp(w), exp(k), exp(k)*v), composed as
// (p2,q2)o(p1,q1) = (p2*p1, p2*q1+q2). Associative -> segment-parallel.
//
// Pass 1: per (channel, segment) local composition (P, A, B), zero init.
// Pass 2: per channel, sequential scan over NSEG segment states -> (a0,b0).
// Pass 3: per (channel, segment) rescan from known (a0,b0), write out = b/a.
//
// B*D = 16384 channels, S = 16 segments -> 262144 threads in passes 1/3
// (~55 warps/SM): BW-bound instead of latency-bound.

#define BATCH 16
#define TLEN  2048
#define DIM   1024
#define CHAN  (BATCH * DIM)      // 16384
#define NSEG  16
#define SEG   (TLEN / NSEG)      // 128
#define UNR   4

// Scratch (allocation-free: __device__ globals). Layout [seg][chan] so that
// index == global thread id in passes 1/3 -> fully coalesced.
__device__ float g_P [NSEG * CHAN];
__device__ float g_A [NSEG * CHAN];
__device__ float g_B [NSEG * CHAN];
__device__ float g_a0[NSEG * CHAN];
__device__ float g_b0[NSEG * CHAN];

// ---------------------------------------------------------------- pass 1
__global__ __launch_bounds__(256)
void wkv_pass1(const float* __restrict__ K,
               const float* __restrict__ V,
               const float* __restrict__ W) {
    const int tid = blockIdx.x * blockDim.x + threadIdx.x;  // 0..NSEG*CHAN-1
    const int s = tid >> 14;            // / CHAN
    const int c = tid & (CHAN - 1);     // % CHAN
    const int b = c >> 10;              // / DIM
    const int d = c & (DIM - 1);        // % DIM

    const size_t base = (size_t)b * TLEN * DIM + (size_t)(s * SEG) * DIM + d;
    const float* kp = K + base;
    const float* vp = V + base;
    const float* wp = W + base;

    float P = 1.0f, a = 0.0f, bb = 0.0f;

    float kb[UNR], vb[UNR], wb[UNR];
#pragma unroll
    for (int i = 0; i < UNR; ++i) {
        kb[i] = kp[i * DIM];
        vb[i] = vp[i * DIM];
        wb[i] = wp[i * DIM];
    }

    const int NCHUNK = SEG / UNR;
    for (int ch = 0; ch < NCHUNK; ++ch) {
        float kn[UNR], vn[UNR], wn[UNR];
        if (ch + 1 < NCHUNK) {
#pragma unroll
            for (int i = 0; i < UNR; ++i) {
                kn[i] = kp[(UNR + i) * DIM];
                vn[i] = vp[(UNR + i) * DIM];
                wn[i] = wp[(UNR + i) * DIM];
            }
        } else {
#pragma unroll
            for (int i = 0; i < UNR; ++i) { kn[i] = 0.f; vn[i] = 0.f; wn[i] = 0.f; }
        }

#pragma unroll
        for (int i = 0; i < UNR; ++i) {
            const float ew = __expf(wb[i]);
            const float ek = __expf(kb[i]);
            P  = P * ew;
            a  = fmaf(ew, a, ek);
            bb = fmaf(ew, bb, ek * vb[i]);
        }

        kp += UNR * DIM; vp += UNR * DIM; wp += UNR * DIM;
#pragma unroll
        for (int i = 0; i < UNR; ++i) { kb[i] = kn[i]; vb[i] = vn[i]; wb[i] = wn[i]; }
    }

    g_P[tid] = P;
    g_A[tid] = a;
    g_B[tid] = bb;
}

// ---------------------------------------------------------------- pass 2
__global__ __launch_bounds__(256)
void wkv_pass2() {
    const int c = blockIdx.x * blockDim.x + threadIdx.x;  // 0..CHAN-1
    float a0 = 0.0f, b0 = 0.0f;
#pragma unroll
    for (int s = 0; s < NSEG; ++s) {
        const int idx = s * CHAN + c;
        g_a0[idx] = a0;
        g_b0[idx] = b0;
        const float p = g_P[idx];
        a0 = fmaf(p, a0, g_A[idx]);
        b0 = fmaf(p, b0, g_B[idx]);
    }
}

// ---------------------------------------------------------------- pass 3
__global__ __launch_bounds__(256)
void wkv_pass3(const float* __restrict__ K,
               const float* __restrict__ V,
               const float* __restrict__ W,
               float* __restrict__ O) {
    const int tid = blockIdx.x * blockDim.x + threadIdx.x;
    const int s = tid >> 14;
    const int c = tid & (CHAN - 1);
    const int b = c >> 10;
    const int d = c & (DIM - 1);

    const size_t base = (size_t)b * TLEN * DIM + (size_t)(s * SEG) * DIM + d;
    const float* kp = K + base;
    const float* vp = V + base;
    const float* wp = W + base;
    float*       op = O + base;

    float a  = g_a0[tid];
    float bb = g_b0[tid];

    float kb[UNR], vb[UNR], wb[UNR];
#pragma unroll
    for (int i = 0; i < UNR; ++i) {
        kb[i] = kp[i * DIM];
        vb[i] = vp[i * DIM];
        wb[i] = wp[i * DIM];
    }

    const int NCHUNK = SEG / UNR;
    for (int ch = 0; ch < NCHUNK; ++ch) {
        float kn[UNR], vn[UNR], wn[UNR];
        if (ch + 1 < NCHUNK) {
#pragma unroll
            for (int i = 0; i < UNR; ++i) {
                kn[i] = kp[(UNR + i) * DIM];
                vn[i] = vp[(UNR + i) * DIM];
                wn[i] = wp[(UNR + i) * DIM];
            }
        } else {
#pragma unroll
            for (int i = 0; i < UNR; ++i) { kn[i] = 0.f; vn[i] = 0.f; wn[i] = 0.f; }
        }

#pragma unroll
        for (int i = 0; i < UNR; ++i) {
            const float ew = __expf(wb[i]);
            const float ek = __expf(kb[i]);
            a  = fmaf(ew, a, ek);
            bb = fmaf(ew, bb, ek * vb[i]);
            op[i * DIM] = __fdividef(bb, a);
        }

        kp += UNR * DIM; vp += UNR * DIM; wp += UNR * DIM; op += UNR * DIM;
#pragma unroll
        for (int i = 0; i < UNR; ++i) { kb[i] = kn[i]; vb[i] = vn[i]; wb[i] = wn[i]; }
    }
}

// ---------------------------------------------------------------- launch
extern "C" void kernel_launch(void* const* d_in, const int* in_sizes, int n_in,
                              void* d_out, int out_size) {
    const float* K = (const float*)d_in[0];
    const float* V = (const float*)d_in[1];
    const float* W = (const float*)d_in[2];
    float*       O = (float*)d_out;

    const int threads = 256;
    const int work13  = NSEG * CHAN;                 // 262144
    wkv_pass1<<<work13 / threads, threads>>>(K, V, W);
    wkv_pass2<<<CHAN / threads, threads>>>();
    wkv_pass3<<<work13 / threads, threads>>>(K, V, W, O);
}

// round 5
// speedup vs baseline: 1.8892x; 1.1737x over previous
#include <cuda_runtime.h>
#include <cuda_bf16.h>

// Single-pass RWKV WKV scan with decoupled lookback over T-segments.
//
// Per segment, normalize by the running decay product:
//   cw_i = sum_{j<=i} w_j,  e_i = exp(k_i - cw_i)
//   ahat_i = sum e_j, bhat_i = sum e_j v_j
//   out_i = (b0 + bhat_i) / (a0 + ahat_i)        (decay product cancels!)
// Inclusive prefix published for next segment:
//   a_inc = exp(cw_end) * (a0 + ahat_end),  b_inc likewise.
//
// Grid ordered segment-major (all s=0 blocks first) -> standard decoupled-
// lookback forward progress. Inputs read ONCE: ~520 MB total DRAM traffic.

#define BATCH 16
#define TLEN  2048
#define DIM   1024
#define CHAN  (BATCH * DIM)     // 16384
#define SEG   32
#define NSEG  (TLEN / SEG)      // 64
#define BLKC  256               // channels per block
#define NCG   (CHAN / BLKC)     // 64

__device__ float    g_prefA[NSEG * CHAN];
__device__ float    g_prefB[NSEG * CHAN];
__device__ unsigned g_flag [NSEG * NCG];

__global__ void wkv_reset_flags() {
    const int i = blockIdx.x * blockDim.x + threadIdx.x;
    if (i < NSEG * NCG) g_flag[i] = 0u;
}

__global__ __launch_bounds__(BLKC, 2)
void wkv_fused(const float* __restrict__ K,
               const float* __restrict__ V,
               const float* __restrict__ W,
               float* __restrict__ O) {
    const int s   = blockIdx.x / NCG;     // segment (bid segment-major)
    const int cg  = blockIdx.x % NCG;     // channel group
    const int tid = threadIdx.x;
    const int c   = cg * BLKC + tid;      // channel 0..16383
    const int b   = c >> 10;              // / DIM
    const int d   = c & (DIM - 1);        // % DIM

    const size_t base = (size_t)b * TLEN * DIM + (size_t)(s * SEG) * DIM + d;
    const float* kp = K + base;
    const float* vp = V + base;
    const float* wp = W + base;
    float*       op = O + base;

    // Local normalized scan: one exp per step, 2 register arrays.
    float ah[SEG], bh[SEG];
    float cw = 0.0f, aa = 0.0f, bb = 0.0f;
#pragma unroll
    for (int i = 0; i < SEG; ++i) {
        const float ki = kp[i * DIM];
        const float vi = vp[i * DIM];
        const float wi = wp[i * DIM];
        cw += wi;
        const float e = __expf(ki - cw);
        aa += e;
        bb = fmaf(e, vi, bb);
        ah[i] = aa;
        bh[i] = bb;
    }
    const float P = __expf(cw);

    // ---- lookback: wait for inclusive prefix of segment s-1 ----
    float a0 = 0.0f, b0 = 0.0f;
    if (s > 0) {
        if (tid == 0) {
            while (atomicAdd(&g_flag[(s - 1) * NCG + cg], 0u) == 0u)
                __nanosleep(40);
            __threadfence();   // acquire: order prefix loads after flag
        }
        __syncthreads();
        a0 = g_prefA[(size_t)(s - 1) * CHAN + c];
        b0 = g_prefB[(size_t)(s - 1) * CHAN + c];
    }

    // ---- publish own inclusive prefix ASAP (chain critical path) ----
    g_prefA[(size_t)s * CHAN + c] = P * (a0 + aa);
    g_prefB[(size_t)s * CHAN + c] = P * (b0 + bb);
    __threadfence();           // release: prefixes visible before flag
    __syncthreads();           // all 256 channels published
    if (tid == 0) atomicExch(&g_flag[s * NCG + cg], 1u);

    // ---- outputs (off the chain critical path) ----
#pragma unroll
    for (int i = 0; i < SEG; ++i)
        op[i * DIM] = __fdividef(b0 + bh[i], a0 + ah[i]);
}

extern "C" void kernel_launch(void* const* d_in, const int* in_sizes, int n_in,
                              void* d_out, int out_size) {
    const float* K = (const float*)d_in[0];
    const float* V = (const float*)d_in[1];
    const float* W = (const float*)d_in[2];
    float*       O = (float*)d_out;

    wkv_reset_flags<<<(NSEG * NCG + 255) / 256, 256>>>();
    wkv_fused<<<NSEG * NCG, BLKC>>>(K, V, W, O);   // 4096 blocks, segment-major
}